// round 16
// baseline (speedup 1.0000x reference)
#include <cuda_runtime.h>
#include <cuda_fp16.h>
#include <math.h>
#include <cstdint>

// ---------------- problem constants ----------------------------------------
constexpr int B   = 8;
constexpr int F   = 8;
constexpr int NS  = 196;
constexpr int NT  = 1 + F*NS;   // 1569
constexpr int D   = 768;
constexpr int H   = 12;
constexpr int HD  = 64;
constexpr int D3  = 3*D;        // 2304
constexpr int D4  = 4*D;        // 3072
constexpr int M   = B*NT;       // 12552
constexpr float LN_EPS = 1e-5f;
constexpr float QSCALE = 0.125f;
constexpr int NSPL = 8;
constexpr int SPAN = (NT + NSPL - 1) / NSPL;  // 197
constexpr int NPERS = 296;      // persistent CTAs (2 x 148 SMs)

// ---------------- scratch (device globals; no allocation) ------------------
__device__ __half g_lnf [(size_t)M * D];
__device__ __half g_qkvh[(size_t)M * D3];
__device__ __half g_attf[(size_t)M * D];
__device__ float  g_tres[(size_t)M * D];
__device__ float  g_sres[(size_t)M * D];
__device__ __half g_hidf[(size_t)M * D4];
__device__ float  g_clsp[B*H*NSPL*66];
// transposed fp16 weights: Wt[n][k] = W[k][n]
__device__ __half g_wf_tqkv [(size_t)D3*D];
__device__ __half g_wf_aqkv [(size_t)D3*D];
__device__ __half g_wf_tproj[(size_t)D*D];
__device__ __half g_wf_aproj[(size_t)D*D];
__device__ __half g_wf_fc1  [(size_t)D4*D];
__device__ __half g_wf_fc2  [(size_t)D*D4];

// ---------------- helpers ----------------------------------------------------
__device__ __forceinline__ uint32_t smem_to_u32(const void* p) {
    uint32_t a;
    asm("{ .reg .u64 t; cvta.to.shared.u64 t, %1; cvt.u32.u64 %0, t; }"
        : "=r"(a) : "l"(p));
    return a;
}
__device__ __forceinline__ void cp_async16(uint32_t dst, const void* src, bool valid) {
    int sz = valid ? 16 : 0;
    asm volatile("cp.async.cg.shared.global [%0], [%1], 16, %2;"
                 :: "r"(dst), "l"(src), "r"(sz) : "memory");
}
#define CP_COMMIT()  asm volatile("cp.async.commit_group;" ::: "memory")
#define CP_WAIT(n)   asm volatile("cp.async.wait_group %0;" :: "n"(n) : "memory")

__device__ __forceinline__ void ldsm_x4(uint32_t& r0, uint32_t& r1, uint32_t& r2, uint32_t& r3, uint32_t addr) {
    asm volatile("ldmatrix.sync.aligned.m8n8.x4.shared.b16 {%0,%1,%2,%3}, [%4];"
                 : "=r"(r0), "=r"(r1), "=r"(r2), "=r"(r3) : "r"(addr));
}
__device__ __forceinline__ void mma_f16(float* c, const uint32_t* a, const uint32_t* b) {
    asm volatile(
        "mma.sync.aligned.m16n8k16.row.col.f32.f16.f16.f32 "
        "{%0,%1,%2,%3}, {%4,%5,%6,%7}, {%8,%9}, {%0,%1,%2,%3};"
        : "+f"(c[0]), "+f"(c[1]), "+f"(c[2]), "+f"(c[3])
        : "r"(a[0]), "r"(a[1]), "r"(a[2]), "r"(a[3]), "r"(b[0]), "r"(b[1]));
}
__device__ __forceinline__ float gelu_exact(float v) {
    return 0.5f * v * (1.f + erff(v * 0.70710678118654752f));
}
__device__ __forceinline__ void unpack8(const uint4& u, float* dst) {
    const __half2* h = (const __half2*)&u;
    #pragma unroll
    for (int j = 0; j < 4; j++) {
        float2 f = __half22float2(h[j]);
        dst[2*j]   = f.x;
        dst[2*j+1] = f.y;
    }
}
__device__ __forceinline__ void load64h(const __half* p, float* dst) {
    const uint4* u = (const uint4*)p;
    #pragma unroll
    for (int i = 0; i < 8; i++) {
        uint4 v = u[i];
        unpack8(v, dst + 8*i);
    }
}

// ========== fp16 persistent GEMM (3-stage, 2 CTAs/SM, staged epilogue) ==========
constexpr int BM = 128, BN = 128, FBK = 64;
constexpr int FRSB = 144;
constexpr int FMAT = 128 * FRSB;        // 18432
constexpr int FSTAGE = 2 * FMAT;        // 36864
constexpr int SMEM_F16 = 3 * FSTAGE;    // 110592 -> 2 CTAs/SM
constexpr int SROWH = 272;
constexpr int SROWF = 528;

// EPI: 1 = bias+residual -> fp32 C ; 4 = bias+GELU -> fp16 Ch ; 5 = bias -> fp16 Ch
template<int EPI>
__global__ void __launch_bounds__(256, 2)
gemm_f16(const __half* __restrict__ A, const __half* __restrict__ Bw,
         const float* __restrict__ bias, const float* __restrict__ R,
         float* __restrict__ C, __half* __restrict__ Ch,
         int Mr, int K, int Nc)
{
    extern __shared__ char smem[];
    const uint32_t sb = smem_to_u32(smem);
    const int tid = threadIdx.x;
    const int wid = tid >> 5, lane = tid & 31;
    const int wm = wid & 1, wn = wid >> 1;

    const int mTiles = (Mr + BM - 1) / BM;
    const int nTiles = Nc / BN;
    const int nTot = mTiles * nTiles;
    const int NC = K / FBK;

    const int aRow = (lane & 15);
    const int aColB = (lane >> 4) * 16;
    const int bMtx = lane >> 3, bRit = lane & 7;
    const int bNrow = (bMtx & 2) ? (8 + bRit) : bRit;
    const int bKoff = (bMtx & 1) * 16;
    const int er = lane >> 2, ec = (lane & 3) * 2;

    for (int tile = blockIdx.x; tile < nTot; tile += NPERS) {
        const int bm = (tile / nTiles) * BM;
        const int bn = (tile % nTiles) * BN;

        float acc[4][4][4];
        #pragma unroll
        for (int i = 0; i < 4; i++)
            #pragma unroll
            for (int j = 0; j < 4; j++)
                #pragma unroll
                for (int q = 0; q < 4; q++) acc[i][j][q] = 0.f;

        auto load_stage = [&](int stage, int k0) {
            uint32_t base = sb + stage * FSTAGE;
            #pragma unroll
            for (int i = 0; i < 4; i++) {
                int idx = tid + i*256;
                int r = idx >> 3, cb = (idx & 7) << 4;
                int gr = bm + r;
                bool v = gr < Mr;
                cp_async16(base + r*FRSB + cb, (const char*)(A + (size_t)(v?gr:0)*K + k0) + cb, v);
            }
            #pragma unroll
            for (int i = 0; i < 4; i++) {
                int idx = tid + i*256;
                int r = idx >> 3, cb = (idx & 7) << 4;
                cp_async16(base + FMAT + r*FRSB + cb, (const char*)(Bw + (size_t)(bn + r)*K + k0) + cb, true);
            }
            CP_COMMIT();
        };

        load_stage(0, 0);
        load_stage(1, FBK);

        int s = 0;
        for (int c = 0; c < NC; c++) {
            if (c + 1 < NC) { CP_WAIT(1); } else { CP_WAIT(0); }
            __syncthreads();
            if (c + 2 < NC) {
                int s2 = s + 2; if (s2 >= 3) s2 -= 3;
                load_stage(s2, (c + 2) * FBK);
            }

            uint32_t aB = sb + s * FSTAGE;
            uint32_t bB = aB + FMAT;

            #pragma unroll
            for (int kk = 0; kk < 4; kk++) {
                uint32_t af[4][4], bf[4][2];
                #pragma unroll
                for (int mt = 0; mt < 4; mt++) {
                    uint32_t off = (uint32_t)((wm*64 + mt*16 + aRow) * FRSB + kk*32 + aColB);
                    ldsm_x4(af[mt][0], af[mt][1], af[mt][2], af[mt][3], aB + off);
                }
                #pragma unroll
                for (int np = 0; np < 2; np++) {
                    uint32_t off = (uint32_t)((wn*32 + np*16 + bNrow) * FRSB + kk*32 + bKoff);
                    ldsm_x4(bf[2*np][0], bf[2*np][1], bf[2*np+1][0], bf[2*np+1][1], bB + off);
                }
                #pragma unroll
                for (int mt = 0; mt < 4; mt++)
                    #pragma unroll
                    for (int nt = 0; nt < 4; nt++)
                        mma_f16(acc[mt][nt], af[mt], bf[nt]);
            }
            if (++s == 3) s = 0;
        }

        // ---------- smem-staged epilogue ----------
        __syncthreads();
        if (EPI == 1) {
            #pragma unroll
            for (int mt = 0; mt < 4; mt++) {
                int r = wm*64 + mt*16 + er;
                #pragma unroll
                for (int nt = 0; nt < 4; nt++) {
                    int cc = wn*32 + nt*8 + ec;
                    float b0 = bias[bn + cc], b1 = bias[bn + cc + 1];
                    *(float2*)(smem + (size_t)r*SROWF + cc*4) =
                        make_float2(acc[mt][nt][0] + b0, acc[mt][nt][1] + b1);
                    *(float2*)(smem + (size_t)(r+8)*SROWF + cc*4) =
                        make_float2(acc[mt][nt][2] + b0, acc[mt][nt][3] + b1);
                }
            }
            __syncthreads();
            #pragma unroll
            for (int i = 0; i < 16; i++) {
                int idx = tid + i*256;
                int row = idx >> 5, cb = (idx & 31) << 4;
                int gr = bm + row;
                if (gr < Mr) {
                    float4 v = *(const float4*)(smem + (size_t)row*SROWF + cb);
                    size_t off = (size_t)gr * Nc + bn + (cb >> 2);
                    float4 rr = *(const float4*)&R[off];
                    v.x += rr.x; v.y += rr.y; v.z += rr.z; v.w += rr.w;
                    *(float4*)&C[off] = v;
                }
            }
        } else {
            #pragma unroll
            for (int mt = 0; mt < 4; mt++) {
                int r = wm*64 + mt*16 + er;
                #pragma unroll
                for (int nt = 0; nt < 4; nt++) {
                    int cc = wn*32 + nt*8 + ec;
                    float b0 = bias[bn + cc], b1 = bias[bn + cc + 1];
                    float v0 = acc[mt][nt][0] + b0, v1 = acc[mt][nt][1] + b1;
                    float v2 = acc[mt][nt][2] + b0, v3 = acc[mt][nt][3] + b1;
                    if (EPI == 4) {
                        v0 = gelu_exact(v0); v1 = gelu_exact(v1);
                        v2 = gelu_exact(v2); v3 = gelu_exact(v3);
                    }
                    *(__half2*)(smem + (size_t)r*SROWH + cc*2)     = __floats2half2_rn(v0, v1);
                    *(__half2*)(smem + (size_t)(r+8)*SROWH + cc*2) = __floats2half2_rn(v2, v3);
                }
            }
            __syncthreads();
            #pragma unroll
            for (int i = 0; i < 8; i++) {
                int idx = tid + i*256;
                int row = idx >> 4, cb = (idx & 15) << 4;
                int gr = bm + row;
                if (gr < Mr)
                    *(uint4*)&Ch[(size_t)gr * Nc + bn + (cb >> 1)] =
                        *(const uint4*)(smem + (size_t)row*SROWH + cb);
            }
        }
        __syncthreads();   // staging smem (aliases stage 0/1) safe to reload next tile
    }
}

// ---------------- LayerNorm -> fp16 -------------------------------------------
__global__ void ln_f16_kernel(const float* __restrict__ X,
                              const float* __restrict__ gam,
                              const float* __restrict__ bet,
                              __half* __restrict__ Y)
{
    int row = blockIdx.x;
    const float* x = X + (size_t)row * D;
    int tid = threadIdx.x;

    float s = 0.f, ss = 0.f;
    for (int i = tid; i < D; i += 256) { float v = x[i]; s += v; ss += v*v; }
    __shared__ float rs[32], rss[32];
    for (int o = 16; o > 0; o >>= 1) {
        s  += __shfl_xor_sync(0xffffffffu, s,  o);
        ss += __shfl_xor_sync(0xffffffffu, ss, o);
    }
    int wid = tid >> 5, lid = tid & 31;
    if (lid == 0) { rs[wid] = s; rss[wid] = ss; }
    __syncthreads();
    __shared__ float s_mean, s_inv;
    if (tid == 0) {
        float ts = 0.f, tss = 0.f;
        for (int w = 0; w < 8; w++) { ts += rs[w]; tss += rss[w]; }
        float mean = ts * (1.f/D);
        float var  = tss * (1.f/D) - mean*mean;
        s_mean = mean; s_inv = rsqrtf(var + LN_EPS);
    }
    __syncthreads();
    float mean = s_mean, inv = s_inv;
    for (int i = tid; i < D; i += 256)
        Y[(size_t)row*D + i] = __float2half((x[i] - mean) * inv * gam[i] + bet[i]);
}

// ---------------- weight transpose -> fp16 -------------------------------------
__global__ void tf16_kernel(const float* __restrict__ W,
                            __half* __restrict__ T, int K, int N)
{
    __shared__ float t[32][33];
    int n0 = blockIdx.x * 32, k0 = blockIdx.y * 32;
    int tx = threadIdx.x, ty = threadIdx.y;
    for (int i = ty; i < 32; i += 8)
        t[i][tx] = W[(size_t)(k0 + i) * N + n0 + tx];
    __syncthreads();
    for (int r = ty; r < 32; r += 8)
        T[(size_t)(n0 + r) * K + k0 + tx] = __float2half(t[tx][r]);
}

// ---------------- cls attention: split-K phase 1 -------------------------------
__global__ void attn_cls_p1(const __half* __restrict__ qkv,
                            float* __restrict__ P)
{
    int bx = blockIdx.x;
    int bh = bx / NSPL, sl = bx % NSPL;
    int b = bh / H, hh = bh % H;
    int tid = threadIdx.x;
    int j0 = sl * SPAN;
    int j1 = min(NT, j0 + SPAN);

    __shared__ float qs[HD];
    __shared__ float sim[SPAN];
    __shared__ float red[256];
    __shared__ float red2[4][HD];

    if (tid < HD)
        qs[tid] = __half2float(qkv[(size_t)(b*NT) * D3 + hh*HD + tid]) * QSCALE;
    __syncthreads();

    float lmx = -1e30f;
    for (int j = j0 + tid; j < j1; j += 256) {
        const __half* kp = qkv + (size_t)(b*NT + j) * D3 + D + hh*HD;
        float kv[64];
        load64h(kp, kv);
        float s = 0.f;
        #pragma unroll
        for (int d = 0; d < HD; d++) s += qs[d] * kv[d];
        sim[j - j0] = s;
        lmx = fmaxf(lmx, s);
    }
    red[tid] = lmx; __syncthreads();
    for (int st = 128; st > 0; st >>= 1) {
        if (tid < st) red[tid] = fmaxf(red[tid], red[tid+st]);
        __syncthreads();
    }
    float mx = red[0];
    __syncthreads();

    float ls = 0.f;
    for (int j = j0 + tid; j < j1; j += 256) {
        float e = __expf(sim[j - j0] - mx);
        sim[j - j0] = e;
        ls += e;
    }
    red[tid] = ls; __syncthreads();
    for (int st = 128; st > 0; st >>= 1) {
        if (tid < st) red[tid] += red[tid+st];
        __syncthreads();
    }
    float lsum = red[0];
    __syncthreads();

    int d = tid & 63, p = tid >> 6;
    float acc = 0.f;
    for (int j = j0 + p; j < j1; j += 4)
        acc += sim[j - j0] * __half2float(qkv[(size_t)(b*NT + j) * D3 + 2*D + hh*HD + d]);
    red2[p][d] = acc;
    __syncthreads();
    if (p == 0) {
        float o = red2[0][d] + red2[1][d] + red2[2][d] + red2[3][d];
        float* dst = P + (size_t)(bh*NSPL + sl) * 66;
        dst[d] = o;
        if (d == 0) { dst[64] = mx; dst[65] = lsum; }
    }
}

// ---------------- cls attention: merge phase ----------------------------------
__global__ void attn_cls_p2(const float* __restrict__ P,
                            __half* __restrict__ O)
{
    int bh = blockIdx.x;
    int b = bh / H, hh = bh % H;
    int d = threadIdx.x;   // 64 threads

    const float* base = P + (size_t)bh * NSPL * 66;
    float mg = -1e30f;
    #pragma unroll
    for (int sl = 0; sl < NSPL; sl++) mg = fmaxf(mg, base[sl*66 + 64]);
    float lg = 0.f, og = 0.f;
    #pragma unroll
    for (int sl = 0; sl < NSPL; sl++) {
        float w = __expf(base[sl*66 + 64] - mg);
        lg += base[sl*66 + 65] * w;
        og += base[sl*66 + d] * w;
    }
    O[(size_t)(b*NT) * D + hh*HD + d] = __float2half(og / lg);
}

// ---------------- time attention -----------------------------------------------
__global__ void attn_time_kernel(const __half* __restrict__ qkv,
                                 __half* __restrict__ O)
{
    int qid = blockIdx.x * blockDim.x + threadIdx.x;
    int fr = qid % F;
    int sp = (qid / F) % NS;
    int bh = qid / (F * NS);
    int b = bh / H, hh = bh % H;
    int t = 1 + fr*NS + sp;

    float q[64];
    load64h(qkv + (size_t)(b*NT + t) * D3 + hh*HD, q);
    #pragma unroll
    for (int i = 0; i < 64; i++) q[i] *= QSCALE;

    float sim[F+1];
    #pragma unroll
    for (int j = 0; j < F+1; j++) {
        int tk = (j == 0) ? 0 : (1 + (j-1)*NS + sp);
        float kv[64];
        load64h(qkv + (size_t)(b*NT + tk) * D3 + D + hh*HD, kv);
        float s = 0.f;
        #pragma unroll
        for (int i = 0; i < 64; i++) s += q[i] * kv[i];
        sim[j] = s;
    }
    float mx = sim[0];
    #pragma unroll
    for (int j = 1; j < F+1; j++) mx = fmaxf(mx, sim[j]);
    float l = 0.f;
    #pragma unroll
    for (int j = 0; j < F+1; j++) { sim[j] = __expf(sim[j] - mx); l += sim[j]; }
    float inv = 1.f / l;

    float o[64];
    #pragma unroll
    for (int i = 0; i < 64; i++) o[i] = 0.f;
    #pragma unroll
    for (int j = 0; j < F+1; j++) {
        int tk = (j == 0) ? 0 : (1 + (j-1)*NS + sp);
        float vv[64];
        load64h(qkv + (size_t)(b*NT + tk) * D3 + 2*D + hh*HD, vv);
        float p = sim[j] * inv;
        #pragma unroll
        for (int i = 0; i < 64; i++) o[i] += p * vv[i];
    }
    __half2* op = (__half2*)(O + (size_t)(b*NT + t) * D + hh*HD);
    #pragma unroll
    for (int i = 0; i < 32; i++)
        op[i] = __floats2half2_rn(o[2*i], o[2*i+1]);
}

// ---------------- space attention -----------------------------------------------
__global__ void attn_space_kernel(const __half* __restrict__ qkv,
                                  __half* __restrict__ O)
{
    int bx = blockIdx.x;
    int bh = bx / F, fr = bx % F;
    int b = bh / H, hh = bh % H;
    int tid = threadIdx.x;
    int sp = tid;
    const int NK = NS + 1;

    __shared__ float Ks[64 * HD];
    __shared__ float Vs[64 * HD];

    float q[64], o[64];
    float m = -1e30f, l = 0.f;
    if (sp < NS) {
        load64h(qkv + (size_t)(b*NT + 1 + fr*NS + sp) * D3 + hh*HD, q);
        #pragma unroll
        for (int i = 0; i < 64; i++) { q[i] *= QSCALE; o[i] = 0.f; }
    }

    for (int t0 = 0; t0 < NK; t0 += 64) {
        __syncthreads();
        for (int e = tid; e < 64*32; e += 256) {
            int jj = e >> 5, d2 = e & 31;
            int j = t0 + jj;
            float2 kf = make_float2(0.f, 0.f), vf = kf;
            if (j < NK) {
                int tk = (j == 0) ? 0 : (1 + fr*NS + (j-1));
                const __half2* base = (const __half2*)(qkv + (size_t)(b*NT + tk) * D3 + hh*HD);
                kf = __half22float2(base[(D   >> 1) + d2]);
                vf = __half22float2(base[(2*D >> 1) + d2]);
            }
            Ks[jj*HD + 2*d2] = kf.x; Ks[jj*HD + 2*d2 + 1] = kf.y;
            Vs[jj*HD + 2*d2] = vf.x; Vs[jj*HD + 2*d2 + 1] = vf.y;
        }
        __syncthreads();

        if (sp < NS) {
            int lim = min(64, NK - t0);
            for (int g = 0; g < lim; g += 8) {
                int gl = min(8, lim - g);
                float sg[8];
                float gm = -1e30f;
                for (int j = 0; j < gl; j++) {
                    const float4* kr = (const float4*)&Ks[(g + j) * HD];
                    float s = 0.f;
                    #pragma unroll
                    for (int i = 0; i < 16; i++) {
                        float4 kk = kr[i];
                        s += q[4*i]*kk.x + q[4*i+1]*kk.y + q[4*i+2]*kk.z + q[4*i+3]*kk.w;
                    }
                    sg[j] = s;
                    gm = fmaxf(gm, s);
                }
                float mn = fmaxf(m, gm);
                float fac = __expf(m - mn);
                l *= fac;
                #pragma unroll
                for (int i = 0; i < 64; i++) o[i] *= fac;
                m = mn;
                for (int j = 0; j < gl; j++) {
                    float p = __expf(sg[j] - m);
                    l += p;
                    const float4* vr = (const float4*)&Vs[(g + j) * HD];
                    #pragma unroll
                    for (int i = 0; i < 16; i++) {
                        float4 vv = vr[i];
                        o[4*i]   = fmaf(p, vv.x, o[4*i]);
                        o[4*i+1] = fmaf(p, vv.y, o[4*i+1]);
                        o[4*i+2] = fmaf(p, vv.z, o[4*i+2]);
                        o[4*i+3] = fmaf(p, vv.w, o[4*i+3]);
                    }
                }
            }
        }
    }

    if (sp < NS) {
        float inv = 1.f / l;
        __half2* op = (__half2*)(O + (size_t)(b*NT + 1 + fr*NS + sp) * D + hh*HD);
        #pragma unroll
        for (int i = 0; i < 32; i++)
            op[i] = __floats2half2_rn(o[2*i]*inv, o[2*i+1]*inv);
    }
}

// ---------------- host launch ------------------------------------------------
extern "C" void kernel_launch(void* const* d_in, const int* in_sizes, int n_in,
                              void* d_out, int out_size)
{
    const float* x      = (const float*)d_in[0];
    const float* n1g    = (const float*)d_in[1];
    const float* n1b    = (const float*)d_in[2];
    const float* n2g    = (const float*)d_in[3];
    const float* n2b    = (const float*)d_in[4];
    const float* n3g    = (const float*)d_in[5];
    const float* n3b    = (const float*)d_in[6];
    const float* aqkvw  = (const float*)d_in[7];
    const float* aqkvb  = (const float*)d_in[8];
    const float* aprojw = (const float*)d_in[9];
    const float* aprojb = (const float*)d_in[10];
    const float* tqkvw  = (const float*)d_in[11];
    const float* tqkvb  = (const float*)d_in[12];
    const float* tprojw = (const float*)d_in[13];
    const float* tprojb = (const float*)d_in[14];
    const float* fc1w   = (const float*)d_in[15];
    const float* fc1b   = (const float*)d_in[16];
    const float* fc2w   = (const float*)d_in[17];
    const float* fc2b   = (const float*)d_in[18];
    float* out = (float*)d_out;

    __half *lnf, *attf, *hidf, *qkvh;
    __half *wf_tqkv, *wf_aqkv, *wf_tproj, *wf_aproj, *wf_fc1, *wf_fc2;
    float *btres, *bsres, *clsp;
    cudaGetSymbolAddress((void**)&lnf,  g_lnf);
    cudaGetSymbolAddress((void**)&attf, g_attf);
    cudaGetSymbolAddress((void**)&hidf, g_hidf);
    cudaGetSymbolAddress((void**)&qkvh, g_qkvh);
    cudaGetSymbolAddress((void**)&btres,g_tres);
    cudaGetSymbolAddress((void**)&bsres,g_sres);
    cudaGetSymbolAddress((void**)&clsp, g_clsp);
    cudaGetSymbolAddress((void**)&wf_tqkv, g_wf_tqkv);
    cudaGetSymbolAddress((void**)&wf_aqkv, g_wf_aqkv);
    cudaGetSymbolAddress((void**)&wf_tproj,g_wf_tproj);
    cudaGetSymbolAddress((void**)&wf_aproj,g_wf_aproj);
    cudaGetSymbolAddress((void**)&wf_fc1,  g_wf_fc1);
    cudaGetSymbolAddress((void**)&wf_fc2,  g_wf_fc2);

    cudaFuncSetAttribute(gemm_f16<1>, cudaFuncAttributeMaxDynamicSharedMemorySize, SMEM_F16);
    cudaFuncSetAttribute(gemm_f16<4>, cudaFuncAttributeMaxDynamicSharedMemorySize, SMEM_F16);
    cudaFuncSetAttribute(gemm_f16<5>, cudaFuncAttributeMaxDynamicSharedMemorySize, SMEM_F16);

    dim3 tb(32, 8);
    const int nTimeBlocks = (B*H*NS*F) / 256;   // 588

    tf16_kernel<<<dim3(D3/32, D/32), tb>>>(tqkvw, wf_tqkv, D, D3);
    tf16_kernel<<<dim3(D3/32, D/32), tb>>>(aqkvw, wf_aqkv, D, D3);
    tf16_kernel<<<dim3(D/32,  D/32), tb>>>(tprojw, wf_tproj, D, D);
    tf16_kernel<<<dim3(D/32,  D/32), tb>>>(aprojw, wf_aproj, D, D);
    ln_f16_kernel<<<M, 256>>>(x, n3g, n3b, lnf);
    gemm_f16<5><<<NPERS, 256, SMEM_F16>>>(lnf, wf_tqkv, tqkvb, nullptr, nullptr, qkvh, M, D, D3);
    attn_cls_p1<<<B*H*NSPL, 256>>>(qkvh, clsp);
    attn_cls_p2<<<B*H, 64>>>(clsp, attf);
    attn_time_kernel<<<nTimeBlocks, 256>>>(qkvh, attf);
    gemm_f16<1><<<NPERS, 256, SMEM_F16>>>(attf, wf_tproj, tprojb, x, btres, nullptr, M, D, D);

    // ---- space attention branch ----
    ln_f16_kernel<<<M, 256>>>(btres, n1g, n1b, lnf);
    gemm_f16<5><<<NPERS, 256, SMEM_F16>>>(lnf, wf_aqkv, aqkvb, nullptr, nullptr, qkvh, M, D, D3);
    attn_cls_p1<<<B*H*NSPL, 256>>>(qkvh, clsp);
    attn_cls_p2<<<B*H, 64>>>(clsp, attf);
    attn_space_kernel<<<B*H*F, 256>>>(qkvh, attf);
    gemm_f16<1><<<NPERS, 256, SMEM_F16>>>(attf, wf_aproj, aprojb, x, bsres, nullptr, M, D, D);

    // ---- MLP ----
    tf16_kernel<<<dim3(D4/32, D/32), tb>>>(fc1w, wf_fc1, D, D4);
    tf16_kernel<<<dim3(D/32, D4/32), tb>>>(fc2w, wf_fc2, D4, D);
    ln_f16_kernel<<<M, 256>>>(bsres, n2g, n2b, lnf);
    gemm_f16<4><<<NPERS, 256, SMEM_F16>>>(lnf, wf_fc1, fc1b, nullptr, nullptr, hidf, M, D, D4);
    gemm_f16<1><<<NPERS, 256, SMEM_F16>>>(hidf, wf_fc2, fc2b, bsres, out, nullptr, M, D4, D);
}

// round 17
// speedup vs baseline: 1.0835x; 1.0835x over previous
#include <cuda_runtime.h>
#include <cuda_fp16.h>
#include <math.h>
#include <cstdint>

// ---------------- problem constants ----------------------------------------
constexpr int B   = 8;
constexpr int F   = 8;
constexpr int NS  = 196;
constexpr int NT  = 1 + F*NS;   // 1569
constexpr int D   = 768;
constexpr int H   = 12;
constexpr int HD  = 64;
constexpr int D3  = 3*D;        // 2304
constexpr int D4  = 4*D;        // 3072
constexpr int M   = B*NT;       // 12552
constexpr float LN_EPS = 1e-5f;
constexpr float QSCALE = 0.125f;
constexpr int NSPL = 8;
constexpr int SPAN = (NT + NSPL - 1) / NSPL;  // 197

// ---------------- scratch (device globals; no allocation) ------------------
__device__ __half g_lnf [(size_t)M * D];
__device__ __half g_qkvh[(size_t)M * D3];
__device__ __half g_attf[(size_t)M * D];
__device__ float  g_tres[(size_t)M * D];
__device__ float  g_sres[(size_t)M * D];
__device__ __half g_hidf[(size_t)M * D4];
__device__ float  g_clsp[B*H*NSPL*66];
// transposed fp16 weights: Wt[n][k] = W[k][n]
__device__ __half g_wf_tqkv [(size_t)D3*D];
__device__ __half g_wf_aqkv [(size_t)D3*D];
__device__ __half g_wf_tproj[(size_t)D*D];
__device__ __half g_wf_aproj[(size_t)D*D];
__device__ __half g_wf_fc1  [(size_t)D4*D];
__device__ __half g_wf_fc2  [(size_t)D*D4];

// ---------------- helpers ----------------------------------------------------
__device__ __forceinline__ uint32_t smem_to_u32(const void* p) {
    uint32_t a;
    asm("{ .reg .u64 t; cvta.to.shared.u64 t, %1; cvt.u32.u64 %0, t; }"
        : "=r"(a) : "l"(p));
    return a;
}
__device__ __forceinline__ void cp_async16(uint32_t dst, const void* src, bool valid) {
    int sz = valid ? 16 : 0;
    asm volatile("cp.async.cg.shared.global [%0], [%1], 16, %2;"
                 :: "r"(dst), "l"(src), "r"(sz) : "memory");
}
#define CP_COMMIT()  asm volatile("cp.async.commit_group;" ::: "memory")
#define CP_WAIT(n)   asm volatile("cp.async.wait_group %0;" :: "n"(n) : "memory")

__device__ __forceinline__ void ldsm_x4(uint32_t& r0, uint32_t& r1, uint32_t& r2, uint32_t& r3, uint32_t addr) {
    asm volatile("ldmatrix.sync.aligned.m8n8.x4.shared.b16 {%0,%1,%2,%3}, [%4];"
                 : "=r"(r0), "=r"(r1), "=r"(r2), "=r"(r3) : "r"(addr));
}
__device__ __forceinline__ void mma_f16(float* c, const uint32_t* a, const uint32_t* b) {
    asm volatile(
        "mma.sync.aligned.m16n8k16.row.col.f32.f16.f16.f32 "
        "{%0,%1,%2,%3}, {%4,%5,%6,%7}, {%8,%9}, {%0,%1,%2,%3};"
        : "+f"(c[0]), "+f"(c[1]), "+f"(c[2]), "+f"(c[3])
        : "r"(a[0]), "r"(a[1]), "r"(a[2]), "r"(a[3]), "r"(b[0]), "r"(b[1]));
}
__device__ __forceinline__ float gelu_exact(float v) {
    return 0.5f * v * (1.f + erff(v * 0.70710678118654752f));
}
__device__ __forceinline__ void unpack8(const uint4& u, float* dst) {
    const __half2* h = (const __half2*)&u;
    #pragma unroll
    for (int j = 0; j < 4; j++) {
        float2 f = __half22float2(h[j]);
        dst[2*j]   = f.x;
        dst[2*j+1] = f.y;
    }
}
__device__ __forceinline__ void load64h(const __half* p, float* dst) {
    const uint4* u = (const uint4*)p;
    #pragma unroll
    for (int i = 0; i < 8; i++) {
        uint4 v = u[i];
        unpack8(v, dst + 8*i);
    }
}

// ================= fp16 single-pass GEMM (3-stage, 2 CTAs/SM) =================
constexpr int BM = 128, BN = 128, FBK = 64;
constexpr int FRSB = 144;
constexpr int FMAT = 128 * FRSB;        // 18432
constexpr int FSTAGE = 2 * FMAT;        // 36864
constexpr int SMEM_F16 = 3 * FSTAGE;    // 110592 -> 2 CTAs/SM
constexpr int SROWH = 272;
constexpr int SROWF = 528;

// EPI: 1 = bias+residual -> fp32 C ; 4 = bias+GELU -> fp16 Ch ; 5 = bias -> fp16 Ch
template<int EPI>
__global__ void __launch_bounds__(256, 2)
gemm_f16(const __half* __restrict__ A, const __half* __restrict__ Bw,
         const float* __restrict__ bias, const float* __restrict__ R,
         float* __restrict__ C, __half* __restrict__ Ch,
         int Mr, int K, int Nc)
{
    extern __shared__ char smem[];
    const uint32_t sb = smem_to_u32(smem);
    const int tid = threadIdx.x;
    const int wid = tid >> 5, lane = tid & 31;
    const int wm = wid & 1, wn = wid >> 1;
    const int bm = blockIdx.y * BM, bn = blockIdx.x * BN;

    float acc[4][4][4];
    #pragma unroll
    for (int i = 0; i < 4; i++)
        #pragma unroll
        for (int j = 0; j < 4; j++)
            #pragma unroll
            for (int q = 0; q < 4; q++) acc[i][j][q] = 0.f;

    auto load_stage = [&](int stage, int k0) {
        uint32_t base = sb + stage * FSTAGE;
        #pragma unroll
        for (int i = 0; i < 4; i++) {
            int idx = tid + i*256;
            int r = idx >> 3, cb = (idx & 7) << 4;
            int gr = bm + r;
            bool v = gr < Mr;
            cp_async16(base + r*FRSB + cb, (const char*)(A + (size_t)(v?gr:0)*K + k0) + cb, v);
        }
        #pragma unroll
        for (int i = 0; i < 4; i++) {
            int idx = tid + i*256;
            int r = idx >> 3, cb = (idx & 7) << 4;
            cp_async16(base + FMAT + r*FRSB + cb, (const char*)(Bw + (size_t)(bn + r)*K + k0) + cb, true);
        }
        CP_COMMIT();
    };

    const int NC = K / FBK;
    load_stage(0, 0);
    load_stage(1, FBK);

    const int aRow = (lane & 15);
    const int aColB = (lane >> 4) * 16;
    const int bMtx = lane >> 3, bRit = lane & 7;
    const int bNrow = (bMtx & 2) ? (8 + bRit) : bRit;
    const int bKoff = (bMtx & 1) * 16;

    int s = 0;
    for (int c = 0; c < NC; c++) {
        if (c + 1 < NC) { CP_WAIT(1); } else { CP_WAIT(0); }
        __syncthreads();
        if (c + 2 < NC) {
            int s2 = s + 2; if (s2 >= 3) s2 -= 3;
            load_stage(s2, (c + 2) * FBK);
        }

        uint32_t aB = sb + s * FSTAGE;
        uint32_t bB = aB + FMAT;

        #pragma unroll
        for (int kk = 0; kk < 4; kk++) {
            uint32_t af[4][4], bf[4][2];
            #pragma unroll
            for (int mt = 0; mt < 4; mt++) {
                uint32_t off = (uint32_t)((wm*64 + mt*16 + aRow) * FRSB + kk*32 + aColB);
                ldsm_x4(af[mt][0], af[mt][1], af[mt][2], af[mt][3], aB + off);
            }
            #pragma unroll
            for (int np = 0; np < 2; np++) {
                uint32_t off = (uint32_t)((wn*32 + np*16 + bNrow) * FRSB + kk*32 + bKoff);
                ldsm_x4(bf[2*np][0], bf[2*np][1], bf[2*np+1][0], bf[2*np+1][1], bB + off);
            }
            #pragma unroll
            for (int mt = 0; mt < 4; mt++)
                #pragma unroll
                for (int nt = 0; nt < 4; nt++)
                    mma_f16(acc[mt][nt], af[mt], bf[nt]);
        }
        if (++s == 3) s = 0;
    }

    // ---------- smem-staged epilogue ----------
    __syncthreads();
    const int er = lane >> 2, ec = (lane & 3) * 2;

    if (EPI == 1) {
        #pragma unroll
        for (int mt = 0; mt < 4; mt++) {
            int r = wm*64 + mt*16 + er;
            #pragma unroll
            for (int nt = 0; nt < 4; nt++) {
                int cc = wn*32 + nt*8 + ec;
                float b0 = bias[bn + cc], b1 = bias[bn + cc + 1];
                *(float2*)(smem + (size_t)r*SROWF + cc*4) =
                    make_float2(acc[mt][nt][0] + b0, acc[mt][nt][1] + b1);
                *(float2*)(smem + (size_t)(r+8)*SROWF + cc*4) =
                    make_float2(acc[mt][nt][2] + b0, acc[mt][nt][3] + b1);
            }
        }
        __syncthreads();
        #pragma unroll
        for (int i = 0; i < 16; i++) {
            int idx = tid + i*256;
            int row = idx >> 5, cb = (idx & 31) << 4;
            int gr = bm + row;
            if (gr < Mr) {
                float4 v = *(const float4*)(smem + (size_t)row*SROWF + cb);
                size_t off = (size_t)gr * Nc + bn + (cb >> 2);
                float4 rr = *(const float4*)&R[off];
                v.x += rr.x; v.y += rr.y; v.z += rr.z; v.w += rr.w;
                *(float4*)&C[off] = v;
            }
        }
    } else {
        #pragma unroll
        for (int mt = 0; mt < 4; mt++) {
            int r = wm*64 + mt*16 + er;
            #pragma unroll
            for (int nt = 0; nt < 4; nt++) {
                int cc = wn*32 + nt*8 + ec;
                float b0 = bias[bn + cc], b1 = bias[bn + cc + 1];
                float v0 = acc[mt][nt][0] + b0, v1 = acc[mt][nt][1] + b1;
                float v2 = acc[mt][nt][2] + b0, v3 = acc[mt][nt][3] + b1;
                if (EPI == 4) {
                    v0 = gelu_exact(v0); v1 = gelu_exact(v1);
                    v2 = gelu_exact(v2); v3 = gelu_exact(v3);
                }
                *(__half2*)(smem + (size_t)r*SROWH + cc*2)     = __floats2half2_rn(v0, v1);
                *(__half2*)(smem + (size_t)(r+8)*SROWH + cc*2) = __floats2half2_rn(v2, v3);
            }
        }
        __syncthreads();
        #pragma unroll
        for (int i = 0; i < 8; i++) {
            int idx = tid + i*256;
            int row = idx >> 4, cb = (idx & 15) << 4;
            int gr = bm + row;
            if (gr < Mr)
                *(uint4*)&Ch[(size_t)gr * Nc + bn + (cb >> 1)] =
                    *(const uint4*)(smem + (size_t)row*SROWH + cb);
        }
    }
}

// ---------------- LayerNorm -> fp16 -------------------------------------------
__global__ void ln_f16_kernel(const float* __restrict__ X,
                              const float* __restrict__ gam,
                              const float* __restrict__ bet,
                              __half* __restrict__ Y)
{
    int row = blockIdx.x;
    const float* x = X + (size_t)row * D;
    int tid = threadIdx.x;

    float s = 0.f, ss = 0.f;
    for (int i = tid; i < D; i += 256) { float v = x[i]; s += v; ss += v*v; }
    __shared__ float rs[32], rss[32];
    for (int o = 16; o > 0; o >>= 1) {
        s  += __shfl_xor_sync(0xffffffffu, s,  o);
        ss += __shfl_xor_sync(0xffffffffu, ss, o);
    }
    int wid = tid >> 5, lid = tid & 31;
    if (lid == 0) { rs[wid] = s; rss[wid] = ss; }
    __syncthreads();
    __shared__ float s_mean, s_inv;
    if (tid == 0) {
        float ts = 0.f, tss = 0.f;
        for (int w = 0; w < 8; w++) { ts += rs[w]; tss += rss[w]; }
        float mean = ts * (1.f/D);
        float var  = tss * (1.f/D) - mean*mean;
        s_mean = mean; s_inv = rsqrtf(var + LN_EPS);
    }
    __syncthreads();
    float mean = s_mean, inv = s_inv;
    for (int i = tid; i < D; i += 256)
        Y[(size_t)row*D + i] = __float2half((x[i] - mean) * inv * gam[i] + bet[i]);
}

// ---------------- fused weight transpose -> fp16 (all six weights) -------------
struct WJob { const float* W; __half* T; int K; int N; int tileOff; };

__global__ void tf16_all_kernel(WJob j0, WJob j1, WJob j2, WJob j3, WJob j4, WJob j5)
{
    __shared__ float t[32][33];
    int bid = blockIdx.x;
    WJob j;
    if      (bid < j1.tileOff) j = j0;
    else if (bid < j2.tileOff) j = j1;
    else if (bid < j3.tileOff) j = j2;
    else if (bid < j4.tileOff) j = j3;
    else if (bid < j5.tileOff) j = j4;
    else                       j = j5;
    int lt = bid - j.tileOff;
    int ntn = j.N / 32;
    int n0 = (lt % ntn) * 32, k0 = (lt / ntn) * 32;

    int tx = threadIdx.x, ty = threadIdx.y;
    for (int i = ty; i < 32; i += 8)
        t[i][tx] = j.W[(size_t)(k0 + i) * j.N + n0 + tx];
    __syncthreads();
    for (int r = ty; r < 32; r += 8)
        j.T[(size_t)(n0 + r) * j.K + k0 + tx] = __float2half(t[tx][r]);
}

// ---------------- cls attention: split-K phase 1 -------------------------------
__global__ void attn_cls_p1(const __half* __restrict__ qkv,
                            float* __restrict__ P)
{
    int bx = blockIdx.x;
    int bh = bx / NSPL, sl = bx % NSPL;
    int b = bh / H, hh = bh % H;
    int tid = threadIdx.x;
    int j0 = sl * SPAN;
    int j1 = min(NT, j0 + SPAN);

    __shared__ float qs[HD];
    __shared__ float sim[SPAN];
    __shared__ float red[256];
    __shared__ float red2[4][HD];

    if (tid < HD)
        qs[tid] = __half2float(qkv[(size_t)(b*NT) * D3 + hh*HD + tid]) * QSCALE;
    __syncthreads();

    float lmx = -1e30f;
    for (int j = j0 + tid; j < j1; j += 256) {
        const __half* kp = qkv + (size_t)(b*NT + j) * D3 + D + hh*HD;
        float kv[64];
        load64h(kp, kv);
        float s = 0.f;
        #pragma unroll
        for (int d = 0; d < HD; d++) s += qs[d] * kv[d];
        sim[j - j0] = s;
        lmx = fmaxf(lmx, s);
    }
    red[tid] = lmx; __syncthreads();
    for (int st = 128; st > 0; st >>= 1) {
        if (tid < st) red[tid] = fmaxf(red[tid], red[tid+st]);
        __syncthreads();
    }
    float mx = red[0];
    __syncthreads();

    float ls = 0.f;
    for (int j = j0 + tid; j < j1; j += 256) {
        float e = __expf(sim[j - j0] - mx);
        sim[j - j0] = e;
        ls += e;
    }
    red[tid] = ls; __syncthreads();
    for (int st = 128; st > 0; st >>= 1) {
        if (tid < st) red[tid] += red[tid+st];
        __syncthreads();
    }
    float lsum = red[0];
    __syncthreads();

    int d = tid & 63, p = tid >> 6;
    float acc = 0.f;
    for (int j = j0 + p; j < j1; j += 4)
        acc += sim[j - j0] * __half2float(qkv[(size_t)(b*NT + j) * D3 + 2*D + hh*HD + d]);
    red2[p][d] = acc;
    __syncthreads();
    if (p == 0) {
        float o = red2[0][d] + red2[1][d] + red2[2][d] + red2[3][d];
        float* dst = P + (size_t)(bh*NSPL + sl) * 66;
        dst[d] = o;
        if (d == 0) { dst[64] = mx; dst[65] = lsum; }
    }
}

// ---------------- cls attention: merge phase ----------------------------------
__global__ void attn_cls_p2(const float* __restrict__ P,
                            __half* __restrict__ O)
{
    int bh = blockIdx.x;
    int b = bh / H, hh = bh % H;
    int d = threadIdx.x;   // 64 threads

    const float* base = P + (size_t)bh * NSPL * 66;
    float mg = -1e30f;
    #pragma unroll
    for (int sl = 0; sl < NSPL; sl++) mg = fmaxf(mg, base[sl*66 + 64]);
    float lg = 0.f, og = 0.f;
    #pragma unroll
    for (int sl = 0; sl < NSPL; sl++) {
        float w = __expf(base[sl*66 + 64] - mg);
        lg += base[sl*66 + 65] * w;
        og += base[sl*66 + d] * w;
    }
    O[(size_t)(b*NT) * D + hh*HD + d] = __float2half(og / lg);
}

// ---------------- time attention -----------------------------------------------
__global__ void attn_time_kernel(const __half* __restrict__ qkv,
                                 __half* __restrict__ O)
{
    int qid = blockIdx.x * blockDim.x + threadIdx.x;
    int fr = qid % F;
    int sp = (qid / F) % NS;
    int bh = qid / (F * NS);
    int b = bh / H, hh = bh % H;
    int t = 1 + fr*NS + sp;

    float q[64];
    load64h(qkv + (size_t)(b*NT + t) * D3 + hh*HD, q);
    #pragma unroll
    for (int i = 0; i < 64; i++) q[i] *= QSCALE;

    float sim[F+1];
    #pragma unroll
    for (int j = 0; j < F+1; j++) {
        int tk = (j == 0) ? 0 : (1 + (j-1)*NS + sp);
        float kv[64];
        load64h(qkv + (size_t)(b*NT + tk) * D3 + D + hh*HD, kv);
        float s = 0.f;
        #pragma unroll
        for (int i = 0; i < 64; i++) s += q[i] * kv[i];
        sim[j] = s;
    }
    float mx = sim[0];
    #pragma unroll
    for (int j = 1; j < F+1; j++) mx = fmaxf(mx, sim[j]);
    float l = 0.f;
    #pragma unroll
    for (int j = 0; j < F+1; j++) { sim[j] = __expf(sim[j] - mx); l += sim[j]; }
    float inv = 1.f / l;

    float o[64];
    #pragma unroll
    for (int i = 0; i < 64; i++) o[i] = 0.f;
    #pragma unroll
    for (int j = 0; j < F+1; j++) {
        int tk = (j == 0) ? 0 : (1 + (j-1)*NS + sp);
        float vv[64];
        load64h(qkv + (size_t)(b*NT + tk) * D3 + 2*D + hh*HD, vv);
        float p = sim[j] * inv;
        #pragma unroll
        for (int i = 0; i < 64; i++) o[i] += p * vv[i];
    }
    __half2* op = (__half2*)(O + (size_t)(b*NT + t) * D + hh*HD);
    #pragma unroll
    for (int i = 0; i < 32; i++)
        op[i] = __floats2half2_rn(o[2*i], o[2*i+1]);
}

// ---------------- space attention -----------------------------------------------
__global__ void attn_space_kernel(const __half* __restrict__ qkv,
                                  __half* __restrict__ O)
{
    int bx = blockIdx.x;
    int bh = bx / F, fr = bx % F;
    int b = bh / H, hh = bh % H;
    int tid = threadIdx.x;
    int sp = tid;
    const int NK = NS + 1;

    __shared__ float Ks[64 * HD];
    __shared__ float Vs[64 * HD];

    float q[64], o[64];
    float m = -1e30f, l = 0.f;
    if (sp < NS) {
        load64h(qkv + (size_t)(b*NT + 1 + fr*NS + sp) * D3 + hh*HD, q);
        #pragma unroll
        for (int i = 0; i < 64; i++) { q[i] *= QSCALE; o[i] = 0.f; }
    }

    for (int t0 = 0; t0 < NK; t0 += 64) {
        __syncthreads();
        for (int e = tid; e < 64*32; e += 256) {
            int jj = e >> 5, d2 = e & 31;
            int j = t0 + jj;
            float2 kf = make_float2(0.f, 0.f), vf = kf;
            if (j < NK) {
                int tk = (j == 0) ? 0 : (1 + fr*NS + (j-1));
                const __half2* base = (const __half2*)(qkv + (size_t)(b*NT + tk) * D3 + hh*HD);
                kf = __half22float2(base[(D   >> 1) + d2]);
                vf = __half22float2(base[(2*D >> 1) + d2]);
            }
            Ks[jj*HD + 2*d2] = kf.x; Ks[jj*HD + 2*d2 + 1] = kf.y;
            Vs[jj*HD + 2*d2] = vf.x; Vs[jj*HD + 2*d2 + 1] = vf.y;
        }
        __syncthreads();

        if (sp < NS) {
            int lim = min(64, NK - t0);
            for (int g = 0; g < lim; g += 8) {
                int gl = min(8, lim - g);
                float sg[8];
                float gm = -1e30f;
                for (int j = 0; j < gl; j++) {
                    const float4* kr = (const float4*)&Ks[(g + j) * HD];
                    float s = 0.f;
                    #pragma unroll
                    for (int i = 0; i < 16; i++) {
                        float4 kk = kr[i];
                        s += q[4*i]*kk.x + q[4*i+1]*kk.y + q[4*i+2]*kk.z + q[4*i+3]*kk.w;
                    }
                    sg[j] = s;
                    gm = fmaxf(gm, s);
                }
                float mn = fmaxf(m, gm);
                float fac = __expf(m - mn);
                l *= fac;
                #pragma unroll
                for (int i = 0; i < 64; i++) o[i] *= fac;
                m = mn;
                for (int j = 0; j < gl; j++) {
                    float p = __expf(sg[j] - m);
                    l += p;
                    const float4* vr = (const float4*)&Vs[(g + j) * HD];
                    #pragma unroll
                    for (int i = 0; i < 16; i++) {
                        float4 vv = vr[i];
                        o[4*i]   = fmaf(p, vv.x, o[4*i]);
                        o[4*i+1] = fmaf(p, vv.y, o[4*i+1]);
                        o[4*i+2] = fmaf(p, vv.z, o[4*i+2]);
                        o[4*i+3] = fmaf(p, vv.w, o[4*i+3]);
                    }
                }
            }
        }
    }

    if (sp < NS) {
        float inv = 1.f / l;
        __half2* op = (__half2*)(O + (size_t)(b*NT + 1 + fr*NS + sp) * D + hh*HD);
        #pragma unroll
        for (int i = 0; i < 32; i++)
            op[i] = __floats2half2_rn(o[2*i]*inv, o[2*i+1]*inv);
    }
}

// ---------------- host launch ------------------------------------------------
extern "C" void kernel_launch(void* const* d_in, const int* in_sizes, int n_in,
                              void* d_out, int out_size)
{
    const float* x      = (const float*)d_in[0];
    const float* n1g    = (const float*)d_in[1];
    const float* n1b    = (const float*)d_in[2];
    const float* n2g    = (const float*)d_in[3];
    const float* n2b    = (const float*)d_in[4];
    const float* n3g    = (const float*)d_in[5];
    const float* n3b    = (const float*)d_in[6];
    const float* aqkvw  = (const float*)d_in[7];
    const float* aqkvb  = (const float*)d_in[8];
    const float* aprojw = (const float*)d_in[9];
    const float* aprojb = (const float*)d_in[10];
    const float* tqkvw  = (const float*)d_in[11];
    const float* tqkvb  = (const float*)d_in[12];
    const float* tprojw = (const float*)d_in[13];
    const float* tprojb = (const float*)d_in[14];
    const float* fc1w   = (const float*)d_in[15];
    const float* fc1b   = (const float*)d_in[16];
    const float* fc2w   = (const float*)d_in[17];
    const float* fc2b   = (const float*)d_in[18];
    float* out = (float*)d_out;

    __half *lnf, *attf, *hidf, *qkvh;
    __half *wf_tqkv, *wf_aqkv, *wf_tproj, *wf_aproj, *wf_fc1, *wf_fc2;
    float *btres, *bsres, *clsp;
    cudaGetSymbolAddress((void**)&lnf,  g_lnf);
    cudaGetSymbolAddress((void**)&attf, g_attf);
    cudaGetSymbolAddress((void**)&hidf, g_hidf);
    cudaGetSymbolAddress((void**)&qkvh, g_qkvh);
    cudaGetSymbolAddress((void**)&btres,g_tres);
    cudaGetSymbolAddress((void**)&bsres,g_sres);
    cudaGetSymbolAddress((void**)&clsp, g_clsp);
    cudaGetSymbolAddress((void**)&wf_tqkv, g_wf_tqkv);
    cudaGetSymbolAddress((void**)&wf_aqkv, g_wf_aqkv);
    cudaGetSymbolAddress((void**)&wf_tproj,g_wf_tproj);
    cudaGetSymbolAddress((void**)&wf_aproj,g_wf_aproj);
    cudaGetSymbolAddress((void**)&wf_fc1,  g_wf_fc1);
    cudaGetSymbolAddress((void**)&wf_fc2,  g_wf_fc2);

    cudaFuncSetAttribute(gemm_f16<1>, cudaFuncAttributeMaxDynamicSharedMemorySize, SMEM_F16);
    cudaFuncSetAttribute(gemm_f16<4>, cudaFuncAttributeMaxDynamicSharedMemorySize, SMEM_F16);
    cudaFuncSetAttribute(gemm_f16<5>, cudaFuncAttributeMaxDynamicSharedMemorySize, SMEM_F16);

    const int MT = (M + BM - 1) / BM;    // 99
    dim3 tb(32, 8);
    const int nTimeBlocks = (B*H*NS*F) / 256;   // 588

    // ---- fused weight transposes (one launch) ----
    // tiles: tqkv 1728, aqkv 1728, tproj 576, aproj 576, fc1 2304, fc2 2304
    WJob j0{tqkvw,  wf_tqkv,  D,  D3, 0};
    WJob j1{aqkvw,  wf_aqkv,  D,  D3, 1728};
    WJob j2{tprojw, wf_tproj, D,  D,  3456};
    WJob j3{aprojw, wf_aproj, D,  D,  4032};
    WJob j4{fc1w,   wf_fc1,   D,  D4, 4608};
    WJob j5{fc2w,   wf_fc2,   D4, D,  6912};
    tf16_all_kernel<<<9216, tb>>>(j0, j1, j2, j3, j4, j5);

    // ---- time attention branch ----
    ln_f16_kernel<<<M, 256>>>(x, n3g, n3b, lnf);
    gemm_f16<5><<<dim3(D3/BN, MT), 256, SMEM_F16>>>(lnf, wf_tqkv, tqkvb, nullptr, nullptr, qkvh, M, D, D3);
    attn_cls_p1<<<B*H*NSPL, 256>>>(qkvh, clsp);
    attn_cls_p2<<<B*H, 64>>>(clsp, attf);
    attn_time_kernel<<<nTimeBlocks, 256>>>(qkvh, attf);
    gemm_f16<1><<<dim3(D/BN, MT), 256, SMEM_F16>>>(attf, wf_tproj, tprojb, x, btres, nullptr, M, D, D);

    // ---- space attention branch ----
    ln_f16_kernel<<<M, 256>>>(btres, n1g, n1b, lnf);
    gemm_f16<5><<<dim3(D3/BN, MT), 256, SMEM_F16>>>(lnf, wf_aqkv, aqkvb, nullptr, nullptr, qkvh, M, D, D3);
    attn_cls_p1<<<B*H*NSPL, 256>>>(qkvh, clsp);
    attn_cls_p2<<<B*H, 64>>>(clsp, attf);
    attn_space_kernel<<<B*H*F, 256>>>(qkvh, attf);
    gemm_f16<1><<<dim3(D/BN, MT), 256, SMEM_F16>>>(attf, wf_aproj, aprojb, x, bsres, nullptr, M, D, D);

    // ---- MLP ----
    ln_f16_kernel<<<M, 256>>>(bsres, n2g, n2b, lnf);
    gemm_f16<4><<<dim3(D4/BN, MT), 256, SMEM_F16>>>(lnf, wf_fc1, fc1b, nullptr, nullptr, hidf, M, D, D4);
    gemm_f16<1><<<dim3(D/BN, MT), 256, SMEM_F16>>>(hidf, wf_fc2, fc2b, bsres, out, nullptr, M, D4, D);
}